// round 12
// baseline (speedup 1.0000x reference)
#include <cuda_runtime.h>
#include <cuda_fp16.h>
#include <cstdint>
#include <math.h>

// Problem shape
#define BB 64
#define TT 128
#define DD 512
#define HH 2048

// x pre-converted to fp16, layout [m][t][d] (8MB)
__device__ __half g_xh[(size_t)BB * TT * DD];
// h = gelu(x@W1+b1), fp16, layout [t][m][hidx] (32MB)
__device__ __half g_h[(size_t)TT * BB * HH];
// split-K partials for GEMM2: [kv][m][t][n] fp16 (32MB)
static constexpr int NKV = 4;
__device__ __half g_part[(size_t)NKV * BB * TT * DD];

static constexpr int SA = 40;   // padded SMEM row stride in fp16 (80 B, ldsm conflict-free)
static constexpr int NT = 256;  // 8 warps

// SMEM: two mma stages only (no raw buffers)
static constexpr int S_A   = 0;      // act  [64 m][32 k] fp16 (5120)
static constexpr int S_W   = 5120;   // wgt  [128 n][32 k] fp16 (10240)
static constexpr int STAGE = 15360;
static constexpr int SMEM_BYTES = 2 * STAGE;  // 30720

// ───────────── helpers ─────────────
__device__ __forceinline__ uint32_t smem_u32(const void* p) {
    uint32_t a;
    asm("{ .reg .u64 t; cvta.to.shared.u64 t, %1; cvt.u32.u64 %0, t; }" : "=r"(a) : "l"(p));
    return a;
}
#define CP_ASYNC16(dst, src) \
    asm volatile("cp.async.cg.shared.global [%0], [%1], 16;" :: "r"(dst), "l"(src) : "memory")
#define CP_COMMIT() asm volatile("cp.async.commit_group;" ::: "memory")
#define CP_WAIT0()  asm volatile("cp.async.wait_group 0;" ::: "memory")

__device__ __forceinline__ void ldsm_x4(uint32_t* r, uint32_t addr) {
    asm volatile("ldmatrix.sync.aligned.m8n8.x4.shared.b16 {%0,%1,%2,%3}, [%4];"
                 : "=r"(r[0]), "=r"(r[1]), "=r"(r[2]), "=r"(r[3]) : "r"(addr));
}
__device__ __forceinline__ void mma16816(float* c, const uint32_t* a, uint32_t b0, uint32_t b1) {
    asm volatile("mma.sync.aligned.m16n8k16.row.col.f32.f16.f16.f32 "
                 "{%0,%1,%2,%3}, {%4,%5,%6,%7}, {%8,%9}, {%0,%1,%2,%3};"
                 : "+f"(c[0]), "+f"(c[1]), "+f"(c[2]), "+f"(c[3])
                 : "r"(a[0]), "r"(a[1]), "r"(a[2]), "r"(a[3]), "r"(b0), "r"(b1));
}
__device__ __forceinline__ uint32_t pack_h2(float x, float y) {
    __half2 t = __floats2half2_rn(x, y);
    return *reinterpret_cast<uint32_t*>(&t);
}
__device__ __forceinline__ float gelu_exact(float v) {
    return 0.5f * v * (1.0f + erff(v * 0.70710678118654752440f));
}

// ═══════ unified GEMM: Act (fp16, cp.async) @ W (fp32, register-convert) ═══════
// Per CTA: token t, n-block n0..n0+127, K-slice = blockIdx.z (CPK chunks of 32).
//   FUSE=true : Out = half( gelu(acc + bias) )      (GEMM1 → h)
//   FUSE=false: Out = half( acc ), raw partials     (GEMM2 → part[kv])
template <int K, int NFULL, int ATS, int AMS, int OTS, int OMS, int CPK, bool FUSE>
__global__ void __launch_bounds__(NT, 3)
ffn_gemm(const float* __restrict__ W, const __half* __restrict__ Act,
         const float* __restrict__ bias, __half* __restrict__ Out)
{
    extern __shared__ char smem[];
    const int t = blockIdx.y, n0 = blockIdx.x * 128;
    const int kz = blockIdx.z;
    const int tid = threadIdx.x, wid = tid >> 5, lane = tid & 31;
    const uint32_t sbase = smem_u32(smem);

    const __half* At = Act + (size_t)t * ATS + (size_t)kz * (CPK * 32);
    const float* Wt = W + (size_t)t * K * NFULL + (size_t)(kz * CPK * 32) * NFULL + n0;

    const int mw = (wid >> 2) * 32;
    const int nwarp = (wid & 3) * 32;
    const uint32_t aLaneOff = (uint32_t)(((lane & 15) * SA + (lane >> 4) * 8) * 2);
    const uint32_t bLaneOff = (uint32_t)(((((lane >> 4) << 3) + (lane & 7)) * SA +
                                          (((lane >> 3) & 1) * 8)) * 2);

    const int am = tid >> 2, ak8 = (tid & 3) * 8;   // act cp.async: 64 rows x 8 halves
    const int wn = tid & 127, wkg = tid >> 7;       // W: column n, 16-row k-group

    float acc[32];
#pragma unroll
    for (int i = 0; i < 32; i++) acc[i] = 0.0f;

    float pw[16];                                    // W prefetch (registers)

    auto AACT = [&](int c, int s) {
        uint32_t dst = sbase + s * STAGE + S_A + am * (SA * 2) + ak8 * 2;
        const __half* src = At + (size_t)am * AMS + c * 32 + ak8;
        CP_ASYNC16(dst, src);
    };
    auto LOADW = [&](int c) {
        const float* p = Wt + (size_t)(c * 32 + wkg * 16) * NFULL + wn;
#pragma unroll
        for (int r = 0; r < 16; r++) pw[r] = p[(size_t)r * NFULL];
    };
    auto STOREW = [&](int s) {
        char* st = smem + s * STAGE;
        uint32_t hw[8];
#pragma unroll
        for (int r = 0; r < 8; r++) hw[r] = pack_h2(pw[2 * r], pw[2 * r + 1]);
        int bo = wn * (SA * 2) + wkg * 32;
        *reinterpret_cast<uint4*>(st + S_W + bo)      = make_uint4(hw[0], hw[1], hw[2], hw[3]);
        *reinterpret_cast<uint4*>(st + S_W + bo + 16) = make_uint4(hw[4], hw[5], hw[6], hw[7]);
    };
    auto MMA = [&](int s) {
        const uint32_t ab = sbase + s * STAGE;
        const uint32_t aB = ab + S_A + mw * (SA * 2) + aLaneOff;
        const uint32_t bB = ab + S_W + nwarp * (SA * 2) + bLaneOff;
#pragma unroll
        for (int ks = 0; ks < 2; ks++) {
            uint32_t ah[2][4];
#pragma unroll
            for (int mf = 0; mf < 2; mf++)
                ldsm_x4(ah[mf], aB + mf * (16 * SA * 2) + ks * 32);
#pragma unroll
            for (int np = 0; np < 2; np++) {
                uint32_t bh[4];
                ldsm_x4(bh, bB + np * (16 * SA * 2) + ks * 32);
#pragma unroll
                for (int mf = 0; mf < 2; mf++) {
                    float* c0 = acc + ((mf * 2 + np) * 2 + 0) * 4;
                    float* c1 = acc + ((mf * 2 + np) * 2 + 1) * 4;
                    mma16816(c0, ah[mf], bh[0], bh[1]);
                    mma16816(c1, ah[mf], bh[2], bh[3]);
                }
            }
        }
    };

    // prologue: A(0) in flight, W(0) in registers
    AACT(0, 0); CP_COMMIT();
    LOADW(0);
    CP_WAIT0(); __syncthreads();
    STOREW(0);
    __syncthreads();
#pragma unroll 1
    for (int c = 0; c < CPK; c++) {
        if (c + 1 < CPK) {
            AACT(c + 1, (c + 1) & 1);   // stage (c+1)&1 last read by MMA(c-1), bar'd
            LOADW(c + 1);                // LDGs drain under MMA(c)
        }
        CP_COMMIT();
        MMA(c & 1);
        CP_WAIT0();
        __syncthreads();
        if (c + 1 < CPK) STOREW((c + 1) & 1);
        __syncthreads();
    }

    // epilogue
    const int gid = lane >> 2, tig = lane & 3;
    __half* outT = Out + (size_t)kz * ((size_t)BB * TT * NFULL) + (size_t)t * OTS + n0;
    const float* bt = bias + (size_t)t * NFULL + n0;
#pragma unroll
    for (int mf = 0; mf < 2; mf++)
#pragma unroll
        for (int np = 0; np < 2; np++)
#pragma unroll
            for (int atom = 0; atom < 2; atom++) {
                const float* a = acc + ((mf * 2 + np) * 2 + atom) * 4;
                int n = nwarp + np * 16 + atom * 8 + tig * 2;
                int m0 = mw + mf * 16 + gid;
                float v00 = a[0], v01 = a[1], v10 = a[2], v11 = a[3];
                if (FUSE) {
                    float bv0 = bt[n], bv1 = bt[n + 1];
                    v00 = gelu_exact(v00 + bv0); v01 = gelu_exact(v01 + bv1);
                    v10 = gelu_exact(v10 + bv0); v11 = gelu_exact(v11 + bv1);
                }
                *reinterpret_cast<__half2*>(outT + (size_t)m0 * OMS + n) =
                    __floats2half2_rn(v00, v01);
                *reinterpret_cast<__half2*>(outT + (size_t)(m0 + 8) * OMS + n) =
                    __floats2half2_rn(v10, v11);
            }
}

// ═════════════ x fp32 → fp16 pre-convert (8 elems/thread) ═════════════
__global__ void __launch_bounds__(256)
x_convert(const float* __restrict__ X, __half* __restrict__ Xh)
{
    size_t i = (size_t)blockIdx.x * 256 + threadIdx.x;
    float4 a = reinterpret_cast<const float4*>(X)[2 * i];
    float4 b = reinterpret_cast<const float4*>(X)[2 * i + 1];
    uint4 o = make_uint4(pack_h2(a.x, a.y), pack_h2(a.z, a.w),
                         pack_h2(b.x, b.y), pack_h2(b.z, b.w));
    reinterpret_cast<uint4*>(Xh)[i] = o;
}

// ═════════════ reduce: out = sum_kv part[kv] + bias (8 elems/thread) ═════════════
__global__ void __launch_bounds__(256)
ffn_reduce(const __half* __restrict__ Part, const float* __restrict__ bias,
           float* __restrict__ Out)
{
    constexpr size_t N8 = (size_t)BB * TT * DD / 8;
    constexpr uint32_t BMASK8 = (TT * DD / 8) - 1;
    size_t i = (size_t)blockIdx.x * 256 + threadIdx.x;
    const uint4* p = reinterpret_cast<const uint4*>(Part);
    float s[8];
#pragma unroll
    for (int j = 0; j < 8; j++) s[j] = 0.0f;
#pragma unroll
    for (int kv = 0; kv < NKV; kv++) {
        uint4 v = p[i + kv * N8];
        const uint32_t w[4] = {v.x, v.y, v.z, v.w};
#pragma unroll
        for (int j = 0; j < 4; j++) {
            float2 f = __half22float2(*reinterpret_cast<const __half2*>(&w[j]));
            s[2 * j] += f.x;
            s[2 * j + 1] += f.y;
        }
    }
    uint32_t b4 = ((uint32_t)i & BMASK8) * 2;
    float4 bv0 = reinterpret_cast<const float4*>(bias)[b4];
    float4 bv1 = reinterpret_cast<const float4*>(bias)[b4 + 1];
    reinterpret_cast<float4*>(Out)[2 * i] =
        make_float4(s[0] + bv0.x, s[1] + bv0.y, s[2] + bv0.z, s[3] + bv0.w);
    reinterpret_cast<float4*>(Out)[2 * i + 1] =
        make_float4(s[4] + bv1.x, s[5] + bv1.y, s[6] + bv1.z, s[7] + bv1.w);
}

// ───────────── host launcher ─────────────
extern "C" void kernel_launch(void* const* d_in, const int* in_sizes, int n_in,
                              void* d_out, int out_size)
{
    (void)in_sizes; (void)n_in; (void)out_size;
    const float* x  = (const float*)d_in[0];  // [B, T, D]
    const float* W1 = (const float*)d_in[1];  // [T, D, H]
    const float* b1 = (const float*)d_in[2];  // [T, H]
    const float* W2 = (const float*)d_in[3];  // [T, H, D]
    const float* b2 = (const float*)d_in[4];  // [T, D]
    float* out = (float*)d_out;               // [B, T, D]

    __half* xh = nullptr;  cudaGetSymbolAddress((void**)&xh, g_xh);
    __half* h = nullptr;   cudaGetSymbolAddress((void**)&h, g_h);
    __half* part = nullptr; cudaGetSymbolAddress((void**)&part, g_part);

    // 0) x → fp16
    x_convert<<<(BB * TT * DD / 8) / 256, 256>>>(x, xh);

    // 1) GEMM1 + GELU: h[t][m][n] = gelu( sum_d xh[m,t,d] * W1[t][d,n] + b1[t,n] )
    auto k1 = ffn_gemm<DD, HH, DD, TT * DD, BB * HH, HH, DD / 32, true>;
    cudaFuncSetAttribute(k1, cudaFuncAttributeMaxDynamicSharedMemorySize, SMEM_BYTES);
    k1<<<dim3(HH / 128, TT, 1), NT, SMEM_BYTES>>>(W1, xh, b1, h);

    // 2) GEMM2 split-K: part[kv][m][t][n] = sum_{k in kv} h[t][m][k] * W2[t][k,n]
    auto k2 = ffn_gemm<HH, DD, BB * HH, HH, DD, TT * DD, (HH / 32) / NKV, false>;
    cudaFuncSetAttribute(k2, cudaFuncAttributeMaxDynamicSharedMemorySize, SMEM_BYTES);
    k2<<<dim3(DD / 128, TT, NKV), NT, SMEM_BYTES>>>(W2, h, b2, part);

    // 3) reduce + bias
    ffn_reduce<<<(BB * TT * DD / 8) / 256, 256>>>(part, b2, out);
}

// round 13
// speedup vs baseline: 1.0827x; 1.0827x over previous
#include <cuda_runtime.h>
#include <cuda_fp16.h>
#include <cstdint>
#include <math.h>

// Problem shape
#define BB 64
#define TT 128
#define DD 512
#define HH 2048

// x pre-converted to fp16, layout [m][t][d] (8MB)
__device__ __half g_xh[(size_t)BB * TT * DD];
// h = gelu(x@W1+b1), fp16, layout [t][m][hidx] (32MB)
__device__ __half g_h[(size_t)TT * BB * HH];
// split-K partials for GEMM2: [kv][m][t][n] fp16 (32MB)
static constexpr int NKV = 4;
__device__ __half g_part[(size_t)NKV * BB * TT * DD];

static constexpr int SA = 40;   // padded SMEM row stride in fp16 (80 B, ldsm conflict-free)
static constexpr int NT = 256;  // 8 warps

// SMEM layout (bytes): two mma stages + two raw fp32 weight stages
static constexpr int S_A   = 0;      // act  [64 m][32 k] fp16 (5120)
static constexpr int S_W   = 5120;   // wgt  [128 n][32 k] fp16 (10240)
static constexpr int STAGE = 15360;
static constexpr int RAW0  = 2 * STAGE;   // 30720
static constexpr int RAWSZ = 16384;       // 32 k-rows x 128 n-cols fp32
static constexpr int SMEM_BYTES = RAW0 + 2 * RAWSZ;  // 63488

// ───────────── helpers ─────────────
__device__ __forceinline__ uint32_t smem_u32(const void* p) {
    uint32_t a;
    asm("{ .reg .u64 t; cvta.to.shared.u64 t, %1; cvt.u32.u64 %0, t; }" : "=r"(a) : "l"(p));
    return a;
}
#define CP_ASYNC16(dst, src) \
    asm volatile("cp.async.cg.shared.global [%0], [%1], 16;" :: "r"(dst), "l"(src) : "memory")
#define CP_COMMIT() asm volatile("cp.async.commit_group;" ::: "memory")
#define CP_WAIT1()  asm volatile("cp.async.wait_group 1;" ::: "memory")

__device__ __forceinline__ void ldsm_x4(uint32_t* r, uint32_t addr) {
    asm volatile("ldmatrix.sync.aligned.m8n8.x4.shared.b16 {%0,%1,%2,%3}, [%4];"
                 : "=r"(r[0]), "=r"(r[1]), "=r"(r[2]), "=r"(r[3]) : "r"(addr));
}
__device__ __forceinline__ void mma16816(float* c, const uint32_t* a, uint32_t b0, uint32_t b1) {
    asm volatile("mma.sync.aligned.m16n8k16.row.col.f32.f16.f16.f32 "
                 "{%0,%1,%2,%3}, {%4,%5,%6,%7}, {%8,%9}, {%0,%1,%2,%3};"
                 : "+f"(c[0]), "+f"(c[1]), "+f"(c[2]), "+f"(c[3])
                 : "r"(a[0]), "r"(a[1]), "r"(a[2]), "r"(a[3]), "r"(b0), "r"(b1));
}
__device__ __forceinline__ uint32_t pack_h2(float x, float y) {
    __half2 t = __floats2half2_rn(x, y);
    return *reinterpret_cast<uint32_t*>(&t);
}
__device__ __forceinline__ float gelu_exact(float v) {
    return 0.5f * v * (1.0f + erff(v * 0.70710678118654752440f));
}

// ═══════ unified GEMM (R11-G2 skeleton): Act fp16 via cp.async, W fp32 via raw cp.async ═══════
// Per CTA: token t, n-block n0..n0+127, K-slice kz (CPK chunks of 32).
//   FUSE=true : Out = half( gelu(acc + bias) )      (GEMM1 → h)
//   FUSE=false: Out = half( acc ), raw partials     (GEMM2 → part[kz])
template <int K, int NFULL, int ATS, int AMS, int OTS, int OMS, int CPK, bool FUSE>
__global__ void __launch_bounds__(NT)
ffn_gemm(const float* __restrict__ W, const __half* __restrict__ Act,
         const float* __restrict__ bias, __half* __restrict__ Out)
{
    extern __shared__ char smem[];
    const int t = blockIdx.y, n0 = blockIdx.x * 128;
    const int kz = blockIdx.z;
    const int tid = threadIdx.x, wid = tid >> 5, lane = tid & 31;
    const uint32_t sbase = smem_u32(smem);

    const __half* At = Act + (size_t)t * ATS + (size_t)kz * (CPK * 32);
    const float* Wt = W + (size_t)t * K * NFULL + (size_t)(kz * CPK * 32) * NFULL + n0;

    const int mw = (wid >> 2) * 32;
    const int nwarp = (wid & 3) * 32;
    const uint32_t aLaneOff = (uint32_t)(((lane & 15) * SA + (lane >> 4) * 8) * 2);
    const uint32_t bLaneOff = (uint32_t)(((((lane >> 4) << 3) + (lane & 7)) * SA +
                                          (((lane >> 3) & 1) * 8)) * 2);

    const int am = tid >> 2, ak8 = (tid & 3) * 8;   // act cp.async: 64 rows x 8 halves
    const int wn = tid & 127, wkg = tid >> 7;       // W convert: column n, 16-row k-group

    float acc[32];
#pragma unroll
    for (int i = 0; i < 32; i++) acc[i] = 0.0f;

    auto WASYNC = [&](int c, int s) {
        const float* base = Wt + (size_t)(c * 32) * NFULL;
        uint32_t dst = sbase + RAW0 + s * RAWSZ + tid * 16;
#pragma unroll
        for (int j = 0; j < 4; j++) {
            int o = tid + 256 * j;
            const float* src = base + (size_t)(o >> 5) * NFULL + (o & 31) * 4;
            CP_ASYNC16(dst + j * 4096, src);
        }
    };
    auto AACT = [&](int c, int s) {
        uint32_t dst = sbase + s * STAGE + S_A + am * (SA * 2) + ak8 * 2;
        const __half* src = At + (size_t)am * AMS + c * 32 + ak8;
        CP_ASYNC16(dst, src);
    };
    auto CONVW = [&](int s) {
        const float* raw = reinterpret_cast<const float*>(smem + RAW0 + s * RAWSZ);
        char* st = smem + s * STAGE;
        float pw[16];
#pragma unroll
        for (int r = 0; r < 16; r++) pw[r] = raw[(wkg * 16 + r) * 128 + wn];
        uint32_t hw[8];
#pragma unroll
        for (int r = 0; r < 8; r++) hw[r] = pack_h2(pw[2 * r], pw[2 * r + 1]);
        int bo = wn * (SA * 2) + wkg * 32;
        *reinterpret_cast<uint4*>(st + S_W + bo)      = make_uint4(hw[0], hw[1], hw[2], hw[3]);
        *reinterpret_cast<uint4*>(st + S_W + bo + 16) = make_uint4(hw[4], hw[5], hw[6], hw[7]);
    };
    auto MMA = [&](int s) {
        const uint32_t ab = sbase + s * STAGE;
        const uint32_t aB = ab + S_A + mw * (SA * 2) + aLaneOff;
        const uint32_t bB = ab + S_W + nwarp * (SA * 2) + bLaneOff;
#pragma unroll
        for (int ks = 0; ks < 2; ks++) {
            uint32_t ah[2][4];
#pragma unroll
            for (int mf = 0; mf < 2; mf++)
                ldsm_x4(ah[mf], aB + mf * (16 * SA * 2) + ks * 32);
#pragma unroll
            for (int np = 0; np < 2; np++) {
                uint32_t bh[4];
                ldsm_x4(bh, bB + np * (16 * SA * 2) + ks * 32);
#pragma unroll
                for (int mf = 0; mf < 2; mf++) {
                    float* c0 = acc + ((mf * 2 + np) * 2 + 0) * 4;
                    float* c1 = acc + ((mf * 2 + np) * 2 + 1) * 4;
                    mma16816(c0, ah[mf], bh[0], bh[1]);
                    mma16816(c1, ah[mf], bh[2], bh[3]);
                }
            }
        }
    };

    // prologue: act0+W0 (G0), W1 (G1); stage 0 W converted
    AACT(0, 0); WASYNC(0, 0); CP_COMMIT();
    WASYNC(1, 1); CP_COMMIT();
    CP_WAIT1(); __syncthreads();
    CONVW(0);
    __syncthreads();
#pragma unroll 1
    for (int c = 0; c < CPK; c++) {
        if (c + 1 < CPK) AACT(c + 1, (c + 1) & 1);   // A stage (c+1): last read MMA(c-1), bar'd
        CP_COMMIT();                                  // group: act(c+1)
        if (c + 2 < CPK) WASYNC(c + 2, c & 1);        // raw c&1: last read CONVW(c), bar'd
        CP_COMMIT();                                  // group: W(c+2)
        MMA(c & 1);                                   // runs while cp.async drains
        CP_WAIT1();                                   // act(c+1) + raw(c+1) complete
        __syncthreads();
        if (c + 1 < CPK) CONVW((c + 1) & 1);
        __syncthreads();
    }

    // epilogue
    const int gid = lane >> 2, tig = lane & 3;
    __half* outT = Out + (size_t)kz * ((size_t)BB * TT * NFULL) + (size_t)t * OTS + n0;
    const float* bt = bias + (size_t)t * NFULL + n0;
#pragma unroll
    for (int mf = 0; mf < 2; mf++)
#pragma unroll
        for (int np = 0; np < 2; np++)
#pragma unroll
            for (int atom = 0; atom < 2; atom++) {
                const float* a = acc + ((mf * 2 + np) * 2 + atom) * 4;
                int n = nwarp + np * 16 + atom * 8 + tig * 2;
                int m0 = mw + mf * 16 + gid;
                float v00 = a[0], v01 = a[1], v10 = a[2], v11 = a[3];
                if (FUSE) {
                    float bv0 = bt[n], bv1 = bt[n + 1];
                    v00 = gelu_exact(v00 + bv0); v01 = gelu_exact(v01 + bv1);
                    v10 = gelu_exact(v10 + bv0); v11 = gelu_exact(v11 + bv1);
                }
                *reinterpret_cast<__half2*>(outT + (size_t)m0 * OMS + n) =
                    __floats2half2_rn(v00, v01);
                *reinterpret_cast<__half2*>(outT + (size_t)(m0 + 8) * OMS + n) =
                    __floats2half2_rn(v10, v11);
            }
}

// ═════════════ x fp32 → fp16 pre-convert (8 elems/thread) ═════════════
__global__ void __launch_bounds__(256)
x_convert(const float* __restrict__ X, __half* __restrict__ Xh)
{
    size_t i = (size_t)blockIdx.x * 256 + threadIdx.x;
    float4 a = reinterpret_cast<const float4*>(X)[2 * i];
    float4 b = reinterpret_cast<const float4*>(X)[2 * i + 1];
    uint4 o = make_uint4(pack_h2(a.x, a.y), pack_h2(a.z, a.w),
                         pack_h2(b.x, b.y), pack_h2(b.z, b.w));
    reinterpret_cast<uint4*>(Xh)[i] = o;
}

// ═════════════ reduce: out = sum_kv part[kv] + bias (8 elems/thread) ═════════════
__global__ void __launch_bounds__(256)
ffn_reduce(const __half* __restrict__ Part, const float* __restrict__ bias,
           float* __restrict__ Out)
{
    constexpr size_t N8 = (size_t)BB * TT * DD / 8;
    constexpr uint32_t BMASK8 = (TT * DD / 8) - 1;
    size_t i = (size_t)blockIdx.x * 256 + threadIdx.x;
    const uint4* p = reinterpret_cast<const uint4*>(Part);
    float s[8];
#pragma unroll
    for (int j = 0; j < 8; j++) s[j] = 0.0f;
#pragma unroll
    for (int kv = 0; kv < NKV; kv++) {
        uint4 v = p[i + kv * N8];
        const uint32_t w[4] = {v.x, v.y, v.z, v.w};
#pragma unroll
        for (int j = 0; j < 4; j++) {
            float2 f = __half22float2(*reinterpret_cast<const __half2*>(&w[j]));
            s[2 * j] += f.x;
            s[2 * j + 1] += f.y;
        }
    }
    uint32_t b4 = ((uint32_t)i & BMASK8) * 2;
    float4 bv0 = reinterpret_cast<const float4*>(bias)[b4];
    float4 bv1 = reinterpret_cast<const float4*>(bias)[b4 + 1];
    reinterpret_cast<float4*>(Out)[2 * i] =
        make_float4(s[0] + bv0.x, s[1] + bv0.y, s[2] + bv0.z, s[3] + bv0.w);
    reinterpret_cast<float4*>(Out)[2 * i + 1] =
        make_float4(s[4] + bv1.x, s[5] + bv1.y, s[6] + bv1.z, s[7] + bv1.w);
}

// ───────────── host launcher ─────────────
extern "C" void kernel_launch(void* const* d_in, const int* in_sizes, int n_in,
                              void* d_out, int out_size)
{
    (void)in_sizes; (void)n_in; (void)out_size;
    const float* x  = (const float*)d_in[0];  // [B, T, D]
    const float* W1 = (const float*)d_in[1];  // [T, D, H]
    const float* b1 = (const float*)d_in[2];  // [T, H]
    const float* W2 = (const float*)d_in[3];  // [T, H, D]
    const float* b2 = (const float*)d_in[4];  // [T, D]
    float* out = (float*)d_out;               // [B, T, D]

    __half* xh = nullptr;   cudaGetSymbolAddress((void**)&xh, g_xh);
    __half* h = nullptr;    cudaGetSymbolAddress((void**)&h, g_h);
    __half* part = nullptr; cudaGetSymbolAddress((void**)&part, g_part);

    // 0) x → fp16
    x_convert<<<(BB * TT * DD / 8) / 256, 256>>>(x, xh);

    // 1) GEMM1 + GELU: h[t][m][n] = gelu( sum_d xh[m,t,d] * W1[t][d,n] + b1[t,n] )
    auto k1 = ffn_gemm<DD, HH, DD, TT * DD, BB * HH, HH, DD / 32, true>;
    cudaFuncSetAttribute(k1, cudaFuncAttributeMaxDynamicSharedMemorySize, SMEM_BYTES);
    k1<<<dim3(HH / 128, TT, 1), NT, SMEM_BYTES>>>(W1, xh, b1, h);

    // 2) GEMM2 split-K: part[kv][m][t][n] = sum_{k in kv} h[t][m][k] * W2[t][k,n]
    auto k2 = ffn_gemm<HH, DD, BB * HH, HH, DD, TT * DD, (HH / 32) / NKV, false>;
    cudaFuncSetAttribute(k2, cudaFuncAttributeMaxDynamicSharedMemorySize, SMEM_BYTES);
    k2<<<dim3(DD / 128, TT, NKV), NT, SMEM_BYTES>>>(W2, h, b2, part);

    // 3) reduce + bias
    ffn_reduce<<<(BB * TT * DD / 8) / 256, 256>>>(part, b2, out);
}